// round 9
// baseline (speedup 1.0000x reference)
#include <cuda_runtime.h>
#include <cuda_bf16.h>
#include <math.h>

// Problem constants
#define BB 8
#define LL 1024
#define SS 1000
#define DM 1024      // d_model = H*E
#define DL 4096      // d_llm
#define HH 16
#define EE 64

// Scratch (allocation-free rule: __device__ globals)
__device__ float g_Q[(size_t)BB * LL * DM];   // 32 MB  (B*L, H*E)
__device__ float g_K[(size_t)SS * DM];        //  4 MB  (S, H*E)
__device__ float g_V[(size_t)SS * DM];        //  4 MB  (S, H*E)
__device__ float g_X[(size_t)BB * LL * DM];   // 32 MB  (B*L, H*E) attention out

// ---------------------------------------------------------------------------
// Classic fp32 GEMM: C[M,N] = A[M,K] @ B[K,N] + bias[N]
// 128x128 block tile, BK=8, 256 threads, 8x8 micro-tile per thread.
// ---------------------------------------------------------------------------
#define GBM 128
#define GBN 128
#define GBK 8
#define GTM 8
#define GTN 8

__global__ __launch_bounds__(256, 2)
void gemm_bias_kernel(const float* __restrict__ A, const float* __restrict__ B,
                      const float* __restrict__ bias, float* __restrict__ C,
                      int M, int N, int K)
{
    __shared__ float As[GBK][GBM];   // A tile, transposed
    __shared__ float Bs[GBK][GBN];

    const int tid  = threadIdx.x;
    const int tcol = tid & 15;       // 0..15 -> N micro
    const int trow = tid >> 4;       // 0..15 -> M micro
    const int row0 = blockIdx.y * GBM;
    const int col0 = blockIdx.x * GBN;

    // A tile load mapping: 128 rows x 8 cols = 256 float4 (one per thread)
    const int aRow  = tid >> 1;              // 0..127
    const int aCol4 = (tid & 1) * 4;         // 0 or 4
    // B tile load mapping: 8 rows x 128 cols = 256 float4
    const int bRow  = tid >> 5;              // 0..7
    const int bCol4 = (tid & 31) * 4;        // 0..124

    float acc[GTM][GTN];
#pragma unroll
    for (int m = 0; m < GTM; m++)
#pragma unroll
        for (int n = 0; n < GTN; n++) acc[m][n] = 0.f;

    for (int k0 = 0; k0 < K; k0 += GBK) {
        // ---- load A tile (guard M; K is always a multiple of 8) ----
        float4 av = make_float4(0.f, 0.f, 0.f, 0.f);
        {
            int gr = row0 + aRow;
            if (gr < M)
                av = *(const float4*)(A + (size_t)gr * K + k0 + aCol4);
        }
        As[aCol4 + 0][aRow] = av.x;
        As[aCol4 + 1][aRow] = av.y;
        As[aCol4 + 2][aRow] = av.z;
        As[aCol4 + 3][aRow] = av.w;

        // ---- load B tile (N tiles are exact for all our shapes) ----
        {
            int gc = col0 + bCol4;
            float4 bv = make_float4(0.f, 0.f, 0.f, 0.f);
            if (gc < N)
                bv = *(const float4*)(B + (size_t)(k0 + bRow) * N + gc);
            *(float4*)&Bs[bRow][bCol4] = bv;
        }
        __syncthreads();

#pragma unroll
        for (int kk = 0; kk < GBK; kk++) {
            float ra[GTM], rb[GTN];
#pragma unroll
            for (int m = 0; m < GTM; m++) ra[m] = As[kk][trow * GTM + m];
#pragma unroll
            for (int n = 0; n < GTN; n++) rb[n] = Bs[kk][tcol * GTN + n];
#pragma unroll
            for (int m = 0; m < GTM; m++)
#pragma unroll
                for (int n = 0; n < GTN; n++)
                    acc[m][n] += ra[m] * rb[n];
        }
        __syncthreads();
    }

    // ---- epilogue: add bias, store ----
#pragma unroll
    for (int m = 0; m < GTM; m++) {
        int gr = row0 + trow * GTM + m;
        if (gr >= M) continue;
        float* crow = C + (size_t)gr * N + col0 + tcol * GTN;
        const float* brow = bias + col0 + tcol * GTN;
#pragma unroll
        for (int n = 0; n < GTN; n += 4) {
            float4 b4 = *(const float4*)(brow + n);
            float4 c4 = make_float4(acc[m][n + 0] + b4.x,
                                    acc[m][n + 1] + b4.y,
                                    acc[m][n + 2] + b4.z,
                                    acc[m][n + 3] + b4.w);
            *(float4*)(crow + n) = c4;
        }
    }
}

// ---------------------------------------------------------------------------
// Fused attention: for each (b,h), softmax(Q K^T / sqrt(E)) V over S=1000.
// One thread owns one query row (q[64], o[64] in registers, online softmax).
// grid = (L/128, B*H), block = 128.
// ---------------------------------------------------------------------------
#define ATS 64   // S tile

__global__ __launch_bounds__(128)
void attn_kernel(const float* __restrict__ Q, const float* __restrict__ K,
                 const float* __restrict__ V, float* __restrict__ X)
{
    __shared__ float Ks[ATS][EE];
    __shared__ float Vs[ATS][EE];

    const int tid = threadIdx.x;
    const int bh  = blockIdx.y;
    const int b   = bh >> 4;
    const int h   = bh & 15;
    const int l   = blockIdx.x * 128 + tid;
    const size_t r = (size_t)b * LL + l;

    // load q row into registers
    float q[EE];
    {
        const float4* qp = (const float4*)(Q + r * DM + h * EE);
#pragma unroll
        for (int i = 0; i < EE / 4; i++) {
            float4 t = qp[i];
            q[4 * i + 0] = t.x; q[4 * i + 1] = t.y;
            q[4 * i + 2] = t.z; q[4 * i + 3] = t.w;
        }
    }

    float o[EE];
#pragma unroll
    for (int e = 0; e < EE; e++) o[e] = 0.f;
    float mx = -1e30f, ssum = 0.f;
    const float scale = 0.125f;  // 1/sqrt(64)

    for (int s0 = 0; s0 < SS; s0 += ATS) {
        const int cnt = min(ATS, SS - s0);
        __syncthreads();
        // cooperative K/V tile load: 64 rows x 16 float4 each
        for (int i = tid; i < ATS * (EE / 4); i += 128) {
            int row = i >> 4;
            int c4  = (i & 15) * 4;
            float4 kv = make_float4(0.f, 0.f, 0.f, 0.f);
            float4 vv = make_float4(0.f, 0.f, 0.f, 0.f);
            if (row < cnt) {
                size_t base = (size_t)(s0 + row) * DM + h * EE + c4;
                kv = *(const float4*)(K + base);
                vv = *(const float4*)(V + base);
            }
            *(float4*)&Ks[row][c4] = kv;
            *(float4*)&Vs[row][c4] = vv;
        }
        __syncthreads();

        for (int j = 0; j < cnt; j++) {
            // score = scale * dot(q, K[j])
            float s = 0.f;
            const float4* kr = (const float4*)Ks[j];
#pragma unroll
            for (int i = 0; i < EE / 4; i++) {
                float4 t = kr[i];
                s += q[4 * i + 0] * t.x + q[4 * i + 1] * t.y
                   + q[4 * i + 2] * t.z + q[4 * i + 3] * t.w;
            }
            s *= scale;
            if (s > mx) {                       // rare: rescale running state
                float c = __expf(mx - s);
                ssum *= c;
#pragma unroll
                for (int e = 0; e < EE; e++) o[e] *= c;
                mx = s;
            }
            float p = __expf(s - mx);
            ssum += p;
            const float4* vr = (const float4*)Vs[j];
#pragma unroll
            for (int i = 0; i < EE / 4; i++) {
                float4 t = vr[i];
                o[4 * i + 0] += p * t.x; o[4 * i + 1] += p * t.y;
                o[4 * i + 2] += p * t.z; o[4 * i + 3] += p * t.w;
            }
        }
    }

    const float inv = 1.f / ssum;
    float4* xp = (float4*)(X + r * DM + h * EE);
#pragma unroll
    for (int i = 0; i < EE / 4; i++)
        xp[i] = make_float4(o[4 * i + 0] * inv, o[4 * i + 1] * inv,
                            o[4 * i + 2] * inv, o[4 * i + 3] * inv);
}

// ---------------------------------------------------------------------------
extern "C" void kernel_launch(void* const* d_in, const int* in_sizes, int n_in,
                              void* d_out, int out_size)
{
    const float* tgt = (const float*)d_in[0];   // (B,L,DM)
    const float* src = (const float*)d_in[1];   // (S,DL)
    const float* val = (const float*)d_in[2];   // (S,DL)
    const float* Wq  = (const float*)d_in[3];   // (DM, H*E)
    const float* bq  = (const float*)d_in[4];
    const float* Wk  = (const float*)d_in[5];   // (DL, H*E)
    const float* bk  = (const float*)d_in[6];
    const float* Wv  = (const float*)d_in[7];   // (DL, H*E)
    const float* bv  = (const float*)d_in[8];
    const float* Wo  = (const float*)d_in[9];   // (H*E, DL)
    const float* bo  = (const float*)d_in[10];
    float* out = (float*)d_out;

    float *Qb, *Kb, *Vb, *Xb;
    cudaGetSymbolAddress((void**)&Qb, g_Q);
    cudaGetSymbolAddress((void**)&Kb, g_K);
    cudaGetSymbolAddress((void**)&Vb, g_V);
    cudaGetSymbolAddress((void**)&Xb, g_X);

    // Q = tgt @ Wq + bq            M=8192, N=1024, K=1024
    gemm_bias_kernel<<<dim3(DM / GBN, (BB * LL) / GBM), 256>>>(
        tgt, Wq, bq, Qb, BB * LL, DM, DM);

    // K = src @ Wk + bk            M=1000, N=1024, K=4096
    gemm_bias_kernel<<<dim3(DM / GBN, (SS + GBM - 1) / GBM), 256>>>(
        src, Wk, bk, Kb, SS, DM, DL);

    // V = val @ Wv + bv
    gemm_bias_kernel<<<dim3(DM / GBN, (SS + GBM - 1) / GBM), 256>>>(
        val, Wv, bv, Vb, SS, DM, DL);

    // X = softmax(Q K^T / sqrt(E)) V      per (b,h)
    attn_kernel<<<dim3(LL / 128, BB * HH), 128>>>(Qb, Kb, Vb, Xb);

    // out = X @ Wo + bo            M=8192, N=4096, K=1024
    gemm_bias_kernel<<<dim3(DL / GBN, (BB * LL) / GBM), 256>>>(
        Xb, Wo, bo, out, BB * LL, DL, DM);
}

// round 10
// speedup vs baseline: 1.5560x; 1.5560x over previous
#include <cuda_runtime.h>
#include <cuda_bf16.h>
#include <math.h>
#include <stdint.h>

// Problem constants
#define BB 8
#define LL 1024
#define SS 1000
#define DM 1024      // d_model = H*E
#define DL 4096      // d_llm
#define HH 16
#define EE 64

// Scratch (allocation-free rule: __device__ globals)
__device__ float g_Q[(size_t)BB * LL * DM];   // 32 MB
__device__ float g_K[(size_t)SS * DM];        //  4 MB
__device__ float g_V[(size_t)SS * DM];        //  4 MB
__device__ float g_X[(size_t)BB * LL * DM];   // 32 MB

// ---------------------------------------------------------------------------
// Split-bf16 tensor-core GEMM:  C[M,N] = A[M,K] @ B[K,N] + bias[N]
// fp32 inputs split on the fly: x = hi + lo (both bf16). Product computed as
// Ahi*Bhi + Alo*Bhi + Ahi*Blo with fp32 accumulation (rel err ~1e-5).
// Block tile 128x128, BK=32, 256 threads (8 warps, 2x4), m16n8k16 mma.sync.
// ---------------------------------------------------------------------------
#define PAD 40   // bf16 elements per smem row (32 data + 8 pad) -> conflict-free ldmatrix

__device__ __forceinline__ void split2(float x, __nv_bfloat16& h, __nv_bfloat16& l) {
    h = __float2bfloat16(x);
    l = __float2bfloat16(x - __bfloat162float(h));
}

__device__ __forceinline__ void ldsm4(uint32_t addr, uint32_t& r0, uint32_t& r1,
                                      uint32_t& r2, uint32_t& r3) {
    asm volatile("ldmatrix.sync.aligned.m8n8.x4.shared.b16 {%0,%1,%2,%3}, [%4];"
                 : "=r"(r0), "=r"(r1), "=r"(r2), "=r"(r3) : "r"(addr));
}

__device__ __forceinline__ void mma16816(float* c, const uint32_t* a,
                                         uint32_t b0, uint32_t b1) {
    asm volatile(
        "mma.sync.aligned.m16n8k16.row.col.f32.bf16.bf16.f32 "
        "{%0,%1,%2,%3}, {%4,%5,%6,%7}, {%8,%9}, {%0,%1,%2,%3};"
        : "+f"(c[0]), "+f"(c[1]), "+f"(c[2]), "+f"(c[3])
        : "r"(a[0]), "r"(a[1]), "r"(a[2]), "r"(a[3]), "r"(b0), "r"(b1));
}

__global__ __launch_bounds__(256)
void gemm3_kernel(const float* __restrict__ A, const float* __restrict__ B,
                  const float* __restrict__ bias, float* __restrict__ C,
                  int M, int N, int K,
                  const float* A2, const float* B2,
                  const float* bias2, float* C2)
{
    if (blockIdx.z == 1) { A = A2; B = B2; bias = bias2; C = C2; }

    __shared__ __nv_bfloat16 Ah[128][PAD], Al[128][PAD];
    __shared__ __nv_bfloat16 Bh[128][PAD], Bl[128][PAD];   // stored n-major: Bh[n][k]

    const int tid  = threadIdx.x;
    const int lane = tid & 31;
    const int wid  = tid >> 5;
    const int wm   = wid >> 2;        // 0..1 : 64 rows each
    const int wn   = wid & 3;         // 0..3 : 32 cols each
    const int row0 = blockIdx.y * 128;
    const int col0 = blockIdx.x * 128;

    // A tile cooperative load: 128 rows x 32 k, one thread = 16 floats
    const int aRow = tid >> 1;
    const int aK   = (tid & 1) * 16;
    // B tile cooperative load: 32 k-rows x 128 n, transpose into smem
    const int bK = tid >> 3;
    const int bN = (tid & 7) * 16;

    // ldmatrix lane addressing (shared by A and B fragments)
    const int rF = lane & 15;
    const int cF = (lane >> 4) << 3;

    float acc[4][4][4];
#pragma unroll
    for (int a = 0; a < 4; a++)
#pragma unroll
        for (int b = 0; b < 4; b++)
#pragma unroll
            for (int c = 0; c < 4; c++) acc[a][b][c] = 0.f;

    for (int k0 = 0; k0 < K; k0 += 32) {
        // ---- A tile: load fp32, split to hi/lo bf16 ----
        {
            const bool okA = (row0 + aRow) < M;
            const float* ap = A + (size_t)(row0 + aRow) * K + k0 + aK;
#pragma unroll
            for (int i = 0; i < 4; i++) {
                float4 v = okA ? *(const float4*)(ap + 4 * i)
                               : make_float4(0.f, 0.f, 0.f, 0.f);
                __nv_bfloat16 h0, h1, h2, h3, l0, l1, l2, l3;
                split2(v.x, h0, l0); split2(v.y, h1, l1);
                split2(v.z, h2, l2); split2(v.w, h3, l3);
                int kk = aK + 4 * i;
                *(__nv_bfloat162*)&Ah[aRow][kk]     = __halves2bfloat162(h0, h1);
                *(__nv_bfloat162*)&Ah[aRow][kk + 2] = __halves2bfloat162(h2, h3);
                *(__nv_bfloat162*)&Al[aRow][kk]     = __halves2bfloat162(l0, l1);
                *(__nv_bfloat162*)&Al[aRow][kk + 2] = __halves2bfloat162(l2, l3);
            }
        }
        // ---- B tile: load fp32 row-major [k][n], store transposed [n][k] ----
        {
            const float* bp = B + (size_t)(k0 + bK) * N + col0 + bN;
#pragma unroll
            for (int i = 0; i < 4; i++) {
                float4 v = *(const float4*)(bp + 4 * i);
                int nn = bN + 4 * i;
                __nv_bfloat16 h, l;
                split2(v.x, h, l); Bh[nn + 0][bK] = h; Bl[nn + 0][bK] = l;
                split2(v.y, h, l); Bh[nn + 1][bK] = h; Bl[nn + 1][bK] = l;
                split2(v.z, h, l); Bh[nn + 2][bK] = h; Bl[nn + 2][bK] = l;
                split2(v.w, h, l); Bh[nn + 3][bK] = h; Bl[nn + 3][bK] = l;
            }
        }
        __syncthreads();

#pragma unroll
        for (int kk = 0; kk < 32; kk += 16) {
            uint32_t ah[4][4], al[4][4], bhr[2][4], blr[2][4];
#pragma unroll
            for (int mf = 0; mf < 4; mf++) {
                int r = wm * 64 + mf * 16 + rF;
                ldsm4((uint32_t)__cvta_generic_to_shared(&Ah[r][kk + cF]),
                      ah[mf][0], ah[mf][1], ah[mf][2], ah[mf][3]);
                ldsm4((uint32_t)__cvta_generic_to_shared(&Al[r][kk + cF]),
                      al[mf][0], al[mf][1], al[mf][2], al[mf][3]);
            }
#pragma unroll
            for (int p = 0; p < 2; p++) {
                int n = wn * 32 + p * 16 + rF;
                ldsm4((uint32_t)__cvta_generic_to_shared(&Bh[n][kk + cF]),
                      bhr[p][0], bhr[p][1], bhr[p][2], bhr[p][3]);
                ldsm4((uint32_t)__cvta_generic_to_shared(&Bl[n][kk + cF]),
                      blr[p][0], blr[p][1], blr[p][2], blr[p][3]);
            }
#pragma unroll
            for (int mf = 0; mf < 4; mf++)
#pragma unroll
                for (int nf = 0; nf < 4; nf++) {
                    int p = nf >> 1, q = nf & 1;
                    uint32_t b0h = bhr[p][q], b1h = bhr[p][q + 2];
                    uint32_t b0l = blr[p][q], b1l = blr[p][q + 2];
                    mma16816(acc[mf][nf], ah[mf], b0h, b1h);  // hi*hi
                    mma16816(acc[mf][nf], al[mf], b0h, b1h);  // lo*hi
                    mma16816(acc[mf][nf], ah[mf], b0l, b1l);  // hi*lo
                }
        }
        __syncthreads();
    }

    // ---- epilogue: bias + store ----
#pragma unroll
    for (int mf = 0; mf < 4; mf++) {
        int r = row0 + wm * 64 + mf * 16 + (lane >> 2);
#pragma unroll
        for (int half = 0; half < 2; half++) {
            int rr = r + half * 8;
            if (rr >= M) continue;
            float* crow = C + (size_t)rr * N;
#pragma unroll
            for (int nf = 0; nf < 4; nf++) {
                int cc = col0 + wn * 32 + nf * 8 + (lane & 3) * 2;
                float2 bv = *(const float2*)(bias + cc);
                float2 o;
                o.x = acc[mf][nf][half * 2 + 0] + bv.x;
                o.y = acc[mf][nf][half * 2 + 1] + bv.y;
                *(float2*)(crow + cc) = o;
            }
        }
    }
}

// ---------------------------------------------------------------------------
// Fused attention: per (b,h), softmax(Q K^T / sqrt(E)) V over S=1000.
// One thread per query row, online softmax, K/V tiles through smem.
// ---------------------------------------------------------------------------
#define ATS 64

__global__ __launch_bounds__(128)
void attn_kernel(const float* __restrict__ Q, const float* __restrict__ K,
                 const float* __restrict__ V, float* __restrict__ X)
{
    __shared__ float Ks[ATS][EE];
    __shared__ float Vs[ATS][EE];

    const int tid = threadIdx.x;
    const int bh  = blockIdx.y;
    const int b   = bh >> 4;
    const int h   = bh & 15;
    const int l   = blockIdx.x * 128 + tid;
    const size_t r = (size_t)b * LL + l;

    float q[EE];
    {
        const float4* qp = (const float4*)(Q + r * DM + h * EE);
#pragma unroll
        for (int i = 0; i < EE / 4; i++) {
            float4 t = qp[i];
            q[4 * i + 0] = t.x; q[4 * i + 1] = t.y;
            q[4 * i + 2] = t.z; q[4 * i + 3] = t.w;
        }
    }

    float o[EE];
#pragma unroll
    for (int e = 0; e < EE; e++) o[e] = 0.f;
    float mx = -1e30f, ssum = 0.f;
    const float scale = 0.125f;

    for (int s0 = 0; s0 < SS; s0 += ATS) {
        const int cnt = min(ATS, SS - s0);
        __syncthreads();
        for (int i = tid; i < ATS * (EE / 4); i += 128) {
            int row = i >> 4;
            int c4  = (i & 15) * 4;
            float4 kv = make_float4(0.f, 0.f, 0.f, 0.f);
            float4 vv = make_float4(0.f, 0.f, 0.f, 0.f);
            if (row < cnt) {
                size_t base = (size_t)(s0 + row) * DM + h * EE + c4;
                kv = *(const float4*)(K + base);
                vv = *(const float4*)(V + base);
            }
            *(float4*)&Ks[row][c4] = kv;
            *(float4*)&Vs[row][c4] = vv;
        }
        __syncthreads();

        for (int j = 0; j < cnt; j++) {
            float s = 0.f;
            const float4* kr = (const float4*)Ks[j];
#pragma unroll
            for (int i = 0; i < EE / 4; i++) {
                float4 t = kr[i];
                s += q[4 * i + 0] * t.x + q[4 * i + 1] * t.y
                   + q[4 * i + 2] * t.z + q[4 * i + 3] * t.w;
            }
            s *= scale;
            if (s > mx) {
                float c = __expf(mx - s);
                ssum *= c;
#pragma unroll
                for (int e = 0; e < EE; e++) o[e] *= c;
                mx = s;
            }
            float p = __expf(s - mx);
            ssum += p;
            const float4* vr = (const float4*)Vs[j];
#pragma unroll
            for (int i = 0; i < EE / 4; i++) {
                float4 t = vr[i];
                o[4 * i + 0] += p * t.x; o[4 * i + 1] += p * t.y;
                o[4 * i + 2] += p * t.z; o[4 * i + 3] += p * t.w;
            }
        }
    }

    const float inv = 1.f / ssum;
    float4* xp = (float4*)(X + r * DM + h * EE);
#pragma unroll
    for (int i = 0; i < EE / 4; i++)
        xp[i] = make_float4(o[4 * i + 0] * inv, o[4 * i + 1] * inv,
                            o[4 * i + 2] * inv, o[4 * i + 3] * inv);
}

// ---------------------------------------------------------------------------
extern "C" void kernel_launch(void* const* d_in, const int* in_sizes, int n_in,
                              void* d_out, int out_size)
{
    const float* tgt = (const float*)d_in[0];
    const float* src = (const float*)d_in[1];
    const float* val = (const float*)d_in[2];
    const float* Wq  = (const float*)d_in[3];
    const float* bq  = (const float*)d_in[4];
    const float* Wk  = (const float*)d_in[5];
    const float* bk  = (const float*)d_in[6];
    const float* Wv  = (const float*)d_in[7];
    const float* bv  = (const float*)d_in[8];
    const float* Wo  = (const float*)d_in[9];
    const float* bo  = (const float*)d_in[10];
    float* out = (float*)d_out;

    float *Qb, *Kb, *Vb, *Xb;
    cudaGetSymbolAddress((void**)&Qb, g_Q);
    cudaGetSymbolAddress((void**)&Kb, g_K);
    cudaGetSymbolAddress((void**)&Vb, g_V);
    cudaGetSymbolAddress((void**)&Xb, g_X);

    // Q = tgt @ Wq + bq     M=8192, N=1024, K=1024
    gemm3_kernel<<<dim3(DM / 128, (BB * LL) / 128, 1), 256>>>(
        tgt, Wq, bq, Qb, BB * LL, DM, DM,
        nullptr, nullptr, nullptr, nullptr);

    // K and V projections fused into one 2-deep grid (fills the chip)
    // z=0: K = src @ Wk + bk   z=1: V = val @ Wv + bv   M=1000, N=1024, K=4096
    gemm3_kernel<<<dim3(DM / 128, (SS + 127) / 128, 2), 256>>>(
        src, Wk, bk, Kb, SS, DM, DL,
        val, Wv, bv, Vb);

    // attention
    attn_kernel<<<dim3(LL / 128, BB * HH), 128>>>(Qb, Kb, Vb, Xb);

    // out = X @ Wo + bo     M=8192, N=4096, K=1024
    gemm3_kernel<<<dim3(DL / 128, (BB * LL) / 128, 1), 256>>>(
        Xb, Wo, bo, out, BB * LL, DL, DM,
        nullptr, nullptr, nullptr, nullptr);
}

// round 12
// speedup vs baseline: 2.2001x; 1.4140x over previous
#include <cuda_runtime.h>
#include <cuda_bf16.h>
#include <stdint.h>
#include <math.h>

// Problem constants
#define BB 8
#define LL 1024
#define SS 1000
#define DM 1024      // d_model = H*E
#define DL 4096      // d_llm
#define HH 16
#define EE 64

// ---------------- scratch (__device__ globals; no allocation allowed) -------
__device__ float g_Q[(size_t)BB * LL * DM];   // fp32 Q for attention
__device__ float g_K[(size_t)SS * DM];
__device__ float g_V[(size_t)SS * DM];

// split bf16 operands (hi + lo)
__device__ __nv_bfloat16 g_tgt_h[(size_t)BB * LL * DM];
__device__ __nv_bfloat16 g_tgt_l[(size_t)BB * LL * DM];
__device__ __nv_bfloat16 g_src_h[(size_t)SS * DL];
__device__ __nv_bfloat16 g_src_l[(size_t)SS * DL];
__device__ __nv_bfloat16 g_val_h[(size_t)SS * DL];
__device__ __nv_bfloat16 g_val_l[(size_t)SS * DL];
__device__ __nv_bfloat16 g_Wq_h[(size_t)DM * DM];
__device__ __nv_bfloat16 g_Wq_l[(size_t)DM * DM];
__device__ __nv_bfloat16 g_Wk_h[(size_t)DL * DM];
__device__ __nv_bfloat16 g_Wk_l[(size_t)DL * DM];
__device__ __nv_bfloat16 g_Wv_h[(size_t)DL * DM];
__device__ __nv_bfloat16 g_Wv_l[(size_t)DL * DM];
__device__ __nv_bfloat16 g_Wo_h[(size_t)DM * DL];
__device__ __nv_bfloat16 g_Wo_l[(size_t)DM * DL];
__device__ __nv_bfloat16 g_X_h[(size_t)BB * LL * DM];
__device__ __nv_bfloat16 g_X_l[(size_t)BB * LL * DM];

// ---------------------------------------------------------------------------
// fp32 -> (hi, lo) bf16 split, streaming. 8 floats per thread.
// ---------------------------------------------------------------------------
__global__ __launch_bounds__(256)
void split_kernel(const float4* __restrict__ in, uint4* __restrict__ hi,
                  uint4* __restrict__ lo, int n8)
{
    int i = blockIdx.x * 256 + threadIdx.x;
    if (i >= n8) return;
    float4 a = in[2 * i], b = in[2 * i + 1];
    float f[8] = {a.x, a.y, a.z, a.w, b.x, b.y, b.z, b.w};
    uint32_t hw[4], lw[4];
#pragma unroll
    for (int j = 0; j < 4; j++) {
        __nv_bfloat16 h0 = __float2bfloat16(f[2 * j]);
        __nv_bfloat16 h1 = __float2bfloat16(f[2 * j + 1]);
        __nv_bfloat16 l0 = __float2bfloat16(f[2 * j]     - __bfloat162float(h0));
        __nv_bfloat16 l1 = __float2bfloat16(f[2 * j + 1] - __bfloat162float(h1));
        __nv_bfloat162 H = __halves2bfloat162(h0, h1);
        __nv_bfloat162 L = __halves2bfloat162(l0, l1);
        hw[j] = *reinterpret_cast<uint32_t*>(&H);
        lw[j] = *reinterpret_cast<uint32_t*>(&L);
    }
    hi[i] = make_uint4(hw[0], hw[1], hw[2], hw[3]);
    lo[i] = make_uint4(lw[0], lw[1], lw[2], lw[3]);
}

// ---------------------------------------------------------------------------
// PTX helpers
// ---------------------------------------------------------------------------
__device__ __forceinline__ void cp16(uint32_t dst, const void* src, bool pred) {
    int sz = pred ? 16 : 0;
    asm volatile("cp.async.cg.shared.global [%0], [%1], 16, %2;\n"
                 :: "r"(dst), "l"(src), "r"(sz));
}
__device__ __forceinline__ void cp_commit() {
    asm volatile("cp.async.commit_group;\n");
}
template <int N> __device__ __forceinline__ void cp_wait() {
    asm volatile("cp.async.wait_group %0;\n" :: "n"(N));
}
__device__ __forceinline__ void ldsm4(uint32_t addr, uint32_t& r0, uint32_t& r1,
                                      uint32_t& r2, uint32_t& r3) {
    asm volatile("ldmatrix.sync.aligned.m8n8.x4.shared.b16 {%0,%1,%2,%3}, [%4];"
                 : "=r"(r0), "=r"(r1), "=r"(r2), "=r"(r3) : "r"(addr));
}
__device__ __forceinline__ void ldsm4t(uint32_t addr, uint32_t& r0, uint32_t& r1,
                                       uint32_t& r2, uint32_t& r3) {
    asm volatile("ldmatrix.sync.aligned.m8n8.x4.trans.shared.b16 {%0,%1,%2,%3}, [%4];"
                 : "=r"(r0), "=r"(r1), "=r"(r2), "=r"(r3) : "r"(addr));
}
__device__ __forceinline__ void mma16816(float* c, const uint32_t* a,
                                         uint32_t b0, uint32_t b1) {
    asm volatile(
        "mma.sync.aligned.m16n8k16.row.col.f32.bf16.bf16.f32 "
        "{%0,%1,%2,%3}, {%4,%5,%6,%7}, {%8,%9}, {%0,%1,%2,%3};"
        : "+f"(c[0]), "+f"(c[1]), "+f"(c[2]), "+f"(c[3])
        : "r"(a[0]), "r"(a[1]), "r"(a[2]), "r"(a[3]), "r"(b0), "r"(b1));
}

// ---------------------------------------------------------------------------
// Split-bf16 tensor-core GEMM on pre-split operands.
// C[M,N] = A @ B + bias;  A = Ah+Al ([M][K] bf16), B = Bh+Bl ([K][N] bf16).
// 128x128 tile, BK=32, 256 threads, cp.async double-buffered.
// A smem row-major (PADA), B smem k-major (PADB) + ldmatrix.trans.
// ---------------------------------------------------------------------------
#define PADA 40                 // 32 data + 8 pad bf16  (80 B rows)
#define PADB 136                // 128 data + 8 pad bf16 (272 B rows)
#define A_ST (128 * PADA)       // elems per A stage
#define B_ST (32 * PADB)        // elems per B stage
#define GSMEM ((4 * A_ST + 4 * B_ST) * 2)   // bytes = 75776

__global__ __launch_bounds__(256, 2)
void gemm_sp(const __nv_bfloat16* __restrict__ Ah, const __nv_bfloat16* __restrict__ Al,
             const __nv_bfloat16* __restrict__ Bh, const __nv_bfloat16* __restrict__ Bl,
             const float* __restrict__ bias, float* __restrict__ C,
             int M, int N, int K,
             const __nv_bfloat16* Ah2, const __nv_bfloat16* Al2,
             const __nv_bfloat16* Bh2, const __nv_bfloat16* Bl2,
             const float* bias2, float* C2)
{
    if (blockIdx.z) { Ah = Ah2; Al = Al2; Bh = Bh2; Bl = Bl2; bias = bias2; C = C2; }

    extern __shared__ __nv_bfloat16 sm[];
    __nv_bfloat16* sAh = sm;
    __nv_bfloat16* sAl = sm + 2 * A_ST;
    __nv_bfloat16* sBh = sm + 4 * A_ST;
    __nv_bfloat16* sBl = sm + 4 * A_ST + 2 * B_ST;

    const int tid  = threadIdx.x;
    const int lane = tid & 31;
    const int wid  = tid >> 5;
    const int wm   = wid >> 2;        // 0..1 : 64 rows
    const int wn   = wid & 3;         // 0..3 : 32 cols
    const int row0 = blockIdx.y * 128;
    const int col0 = blockIdx.x * 128;

    // ldmatrix lane addressing
    const int rF = lane & 15;                       // A: row within 16
    const int cF = (lane >> 4) << 3;                // A: k-half
    const int bR = ((lane >> 3) & 1) * 8 + (lane & 7);  // B: k-row within 16
    const int bC = (lane >> 4) << 3;                // B: n-half

    float acc[4][4][4];
#pragma unroll
    for (int a = 0; a < 4; a++)
#pragma unroll
        for (int b = 0; b < 4; b++)
#pragma unroll
            for (int c = 0; c < 4; c++) acc[a][b][c] = 0.f;

    const int KT = K >> 5;

    auto issue = [&](int kt) {
        const int k0 = kt << 5;
        const int st = kt & 1;
        __nv_bfloat16* dAh = sAh + st * A_ST;
        __nv_bfloat16* dAl = sAl + st * A_ST;
        __nv_bfloat16* dBh = sBh + st * B_ST;
        __nv_bfloat16* dBl = sBl + st * B_ST;
#pragma unroll
        for (int i = 0; i < 2; i++) {               // A: 128 rows x 64B
            int c   = tid + (i << 8);
            int row = c >> 2;
            int off = (c & 3) << 3;                 // elems
            bool p  = (row0 + row) < M;
            size_t go = (size_t)(row0 + (p ? row : 0)) * K + k0 + off;
            uint32_t d = (uint32_t)__cvta_generic_to_shared(dAh + row * PADA + off);
            cp16(d, Ah + go, p);
            d = (uint32_t)__cvta_generic_to_shared(dAl + row * PADA + off);
            cp16(d, Al + go, p);
        }
#pragma unroll
        for (int i = 0; i < 2; i++) {               // B: 32 rows x 256B
            int c   = tid + (i << 8);
            int row = c >> 4;
            int off = (c & 15) << 3;
            size_t go = (size_t)(k0 + row) * N + col0 + off;
            uint32_t d = (uint32_t)__cvta_generic_to_shared(dBh + row * PADB + off);
            cp16(d, Bh + go, true);
            d = (uint32_t)__cvta_generic_to_shared(dBl + row * PADB + off);
            cp16(d, Bl + go, true);
        }
        cp_commit();
    };

    auto compute = [&](int st) {
        const __nv_bfloat16* pAh = sAh + st * A_ST;
        const __nv_bfloat16* pAl = sAl + st * A_ST;
        const __nv_bfloat16* pBh = sBh + st * B_ST;
        const __nv_bfloat16* pBl = sBl + st * B_ST;
#pragma unroll
        for (int kk = 0; kk < 32; kk += 16) {
            uint32_t bh[2][4], bl[2][4];
#pragma unroll
            for (int p = 0; p < 2; p++) {
                int rr = kk + bR;
                int cc = wn * 32 + p * 16 + bC;
                ldsm4t((uint32_t)__cvta_generic_to_shared(pBh + rr * PADB + cc),
                       bh[p][0], bh[p][1], bh[p][2], bh[p][3]);
                ldsm4t((uint32_t)__cvta_generic_to_shared(pBl + rr * PADB + cc),
                       bl[p][0], bl[p][1], bl[p][2], bl[p][3]);
            }
#pragma unroll
            for (int mf = 0; mf < 4; mf++) {
                int r = wm * 64 + mf * 16 + rF;
                uint32_t ah[4], al[4];
                ldsm4((uint32_t)__cvta_generic_to_shared(pAh + r * PADA + kk + cF),
                      ah[0], ah[1], ah[2], ah[3]);
                ldsm4((uint32_t)__cvta_generic_to_shared(pAl + r * PADA + kk + cF),
                      al[0], al[1], al[2], al[3]);
#pragma unroll
                for (int p = 0; p < 2; p++) {
                    mma16816(acc[mf][2 * p],     ah, bh[p][0], bh[p][1]);
                    mma16816(acc[mf][2 * p],     al, bh[p][0], bh[p][1]);
                    mma16816(acc[mf][2 * p],     ah, bl[p][0], bl[p][1]);
                    mma16816(acc[mf][2 * p + 1], ah, bh[p][2], bh[p][3]);
                    mma16816(acc[mf][2 * p + 1], al, bh[p][2], bh[p][3]);
                    mma16816(acc[mf][2 * p + 1], ah, bl[p][2], bl[p][3]);
                }
            }
        }
    };

    issue(0);
    for (int kt = 0; kt < KT; kt++) {
        if (kt + 1 < KT) { issue(kt + 1); cp_wait<1>(); }
        else             { cp_wait<0>(); }
        __syncthreads();
        compute(kt & 1);
        __syncthreads();
    }

    // epilogue: bias + store
#pragma unroll
    for (int mf = 0; mf < 4; mf++) {
        int r = row0 + wm * 64 + mf * 16 + (lane >> 2);
#pragma unroll
        for (int half = 0; half < 2; half++) {
            int rr = r + half * 8;
            if (rr >= M) continue;
            float* crow = C + (size_t)rr * N;
#pragma unroll
            for (int nf = 0; nf < 4; nf++) {
                int cc = col0 + wn * 32 + nf * 8 + (lane & 3) * 2;
                float2 bv = *(const float2*)(bias + cc);
                float2 o;
                o.x = acc[mf][nf][half * 2 + 0] + bv.x;
                o.y = acc[mf][nf][half * 2 + 1] + bv.y;
                *(float2*)(crow + cc) = o;
            }
        }
    }
}

// ---------------------------------------------------------------------------
// Fused attention; writes X directly as split bf16 for the Wo GEMM.
// ---------------------------------------------------------------------------
#define ATS 64

__global__ __launch_bounds__(128)
void attn_kernel(const float* __restrict__ Q, const float* __restrict__ K,
                 const float* __restrict__ V,
                 __nv_bfloat16* __restrict__ Xh, __nv_bfloat16* __restrict__ Xl)
{
    __shared__ float Ks[ATS][EE];
    __shared__ float Vs[ATS][EE];

    const int tid = threadIdx.x;
    const int bh  = blockIdx.y;
    const int b   = bh >> 4;
    const int h   = bh & 15;
    const int l   = blockIdx.x * 128 + tid;
    const size_t r = (size_t)b * LL + l;

    float q[EE];
    {
        const float4* qp = (const float4*)(Q + r * DM + h * EE);
#pragma unroll
        for (int i = 0; i < EE / 4; i++) {
            float4 t = qp[i];
            q[4 * i + 0] = t.x; q[4 * i + 1] = t.y;
            q[4 * i + 2] = t.z; q[4 * i + 3] = t.w;
        }
    }

    float o[EE];
#pragma unroll
    for (int e = 0; e < EE; e++) o[e] = 0.f;
    float mx = -1e30f, ssum = 0.f;
    const float scale = 0.125f;

    for (int s0 = 0; s0 < SS; s0 += ATS) {
        const int cnt = min(ATS, SS - s0);
        __syncthreads();
        for (int i = tid; i < ATS * (EE / 4); i += 128) {
            int row = i >> 4;
            int c4  = (i & 15) * 4;
            float4 kv = make_float4(0.f, 0.f, 0.f, 0.f);
            float4 vv = make_float4(0.f, 0.f, 0.f, 0.f);
            if (row < cnt) {
                size_t base = (size_t)(s0 + row) * DM + h * EE + c4;
                kv = *(const float4*)(K + base);
                vv = *(const float4*)(V + base);
            }
            *(float4*)&Ks[row][c4] = kv;
            *(float4*)&Vs[row][c4] = vv;
        }
        __syncthreads();

        for (int j = 0; j < cnt; j++) {
            float s = 0.f;
            const float4* kr = (const float4*)Ks[j];
#pragma unroll
            for (int i = 0; i < EE / 4; i++) {
                float4 t = kr[i];
                s += q[4 * i + 0] * t.x + q[4 * i + 1] * t.y
                   + q[4 * i + 2] * t.z + q[4 * i + 3] * t.w;
            }
            s *= scale;
            if (s > mx) {
                float c = __expf(mx - s);
                ssum *= c;
#pragma unroll
                for (int e = 0; e < EE; e++) o[e] *= c;
                mx = s;
            }
            float p = __expf(s - mx);
            ssum += p;
            const float4* vr = (const float4*)Vs[j];
#pragma unroll
            for (int i = 0; i < EE / 4; i++) {
                float4 t = vr[i];
                o[4 * i + 0] += p * t.x; o[4 * i + 1] += p * t.y;
                o[4 * i + 2] += p * t.z; o[4 * i + 3] += p * t.w;
            }
        }
    }

    const float inv = 1.f / ssum;
    const size_t base = r * DM + h * EE;
#pragma unroll
    for (int i = 0; i < EE / 2; i++) {
        float v0 = o[2 * i] * inv, v1 = o[2 * i + 1] * inv;
        __nv_bfloat16 h0 = __float2bfloat16(v0);
        __nv_bfloat16 h1 = __float2bfloat16(v1);
        __nv_bfloat16 l0 = __float2bfloat16(v0 - __bfloat162float(h0));
        __nv_bfloat16 l1 = __float2bfloat16(v1 - __bfloat162float(h1));
        *(__nv_bfloat162*)(Xh + base + 2 * i) = __halves2bfloat162(h0, h1);
        *(__nv_bfloat162*)(Xl + base + 2 * i) = __halves2bfloat162(l0, l1);
    }
}

// ---------------------------------------------------------------------------
extern "C" void kernel_launch(void* const* d_in, const int* in_sizes, int n_in,
                              void* d_out, int out_size)
{
    const float* tgt = (const float*)d_in[0];
    const float* src = (const float*)d_in[1];
    const float* val = (const float*)d_in[2];
    const float* Wq  = (const float*)d_in[3];
    const float* bq  = (const float*)d_in[4];
    const float* Wk  = (const float*)d_in[5];
    const float* bk  = (const float*)d_in[6];
    const float* Wv  = (const float*)d_in[7];
    const float* bv  = (const float*)d_in[8];
    const float* Wo  = (const float*)d_in[9];
    const float* bo  = (const float*)d_in[10];
    float* out = (float*)d_out;

    float *Qb, *Kb, *Vb;
    cudaGetSymbolAddress((void**)&Qb, g_Q);
    cudaGetSymbolAddress((void**)&Kb, g_K);
    cudaGetSymbolAddress((void**)&Vb, g_V);

    __nv_bfloat16 *tgtH, *tgtL, *srcH, *srcL, *valH, *valL;
    __nv_bfloat16 *WqH, *WqL, *WkH, *WkL, *WvH, *WvL, *WoH, *WoL, *XH, *XL;
    cudaGetSymbolAddress((void**)&tgtH, g_tgt_h); cudaGetSymbolAddress((void**)&tgtL, g_tgt_l);
    cudaGetSymbolAddress((void**)&srcH, g_src_h); cudaGetSymbolAddress((void**)&srcL, g_src_l);
    cudaGetSymbolAddress((void**)&valH, g_val_h); cudaGetSymbolAddress((void**)&valL, g_val_l);
    cudaGetSymbolAddress((void**)&WqH, g_Wq_h);   cudaGetSymbolAddress((void**)&WqL, g_Wq_l);
    cudaGetSymbolAddress((void**)&WkH, g_Wk_h);   cudaGetSymbolAddress((void**)&WkL, g_Wk_l);
    cudaGetSymbolAddress((void**)&WvH, g_Wv_h);   cudaGetSymbolAddress((void**)&WvL, g_Wv_l);
    cudaGetSymbolAddress((void**)&WoH, g_Wo_h);   cudaGetSymbolAddress((void**)&WoL, g_Wo_l);
    cudaGetSymbolAddress((void**)&XH,  g_X_h);    cudaGetSymbolAddress((void**)&XL,  g_X_l);

    cudaFuncSetAttribute(gemm_sp, cudaFuncAttributeMaxDynamicSharedMemorySize, GSMEM);

    // ---- split pre-passes ----
    auto split = [](const float* p, __nv_bfloat16* h, __nv_bfloat16* l, size_t n) {
        int n8 = (int)(n / 8);
        split_kernel<<<(n8 + 255) / 256, 256>>>((const float4*)p, (uint4*)h, (uint4*)l, n8);
    };
    split(tgt, tgtH, tgtL, (size_t)BB * LL * DM);
    split(src, srcH, srcL, (size_t)SS * DL);
    split(val, valH, valL, (size_t)SS * DL);
    split(Wq,  WqH,  WqL,  (size_t)DM * DM);
    split(Wk,  WkH,  WkL,  (size_t)DL * DM);
    split(Wv,  WvH,  WvL,  (size_t)DL * DM);
    split(Wo,  WoH,  WoL,  (size_t)DM * DL);

    // ---- Q = tgt @ Wq + bq    M=8192, N=1024, K=1024 ----
    gemm_sp<<<dim3(DM / 128, (BB * LL) / 128, 1), 256, GSMEM>>>(
        tgtH, tgtL, WqH, WqL, bq, Qb, BB * LL, DM, DM,
        nullptr, nullptr, nullptr, nullptr, nullptr, nullptr);

    // ---- K/V projections fused (z=2)   M=1000, N=1024, K=4096 ----
    gemm_sp<<<dim3(DM / 128, (SS + 127) / 128, 2), 256, GSMEM>>>(
        srcH, srcL, WkH, WkL, bk, Kb, SS, DM, DL,
        valH, valL, WvH, WvL, bv, Vb);

    // ---- attention (writes split X) ----
    attn_kernel<<<dim3(LL / 128, BB * HH), 128>>>(Qb, Kb, Vb, XH, XL);

    // ---- out = X @ Wo + bo    M=8192, N=4096, K=1024 ----
    gemm_sp<<<dim3(DL / 128, (BB * LL) / 128, 1), 256, GSMEM>>>(
        XH, XL, WoH, WoL, bo, out, BB * LL, DL, DM,
        nullptr, nullptr, nullptr, nullptr, nullptr, nullptr);
}

// round 13
// speedup vs baseline: 2.2013x; 1.0006x over previous
#include <cuda_runtime.h>
#include <cuda_bf16.h>
#include <stdint.h>
#include <math.h>

// Problem constants
#define BB 8
#define LL 1024
#define SS 1000
#define DM 1024      // d_model = H*E
#define DL 4096      // d_llm
#define HH 16
#define EE 64

// ---------------- scratch (__device__ globals; no allocation allowed) -------
__device__ float g_Q[(size_t)BB * LL * DM];   // fp32 Q for attention
__device__ float g_K[(size_t)SS * DM];
__device__ float g_V[(size_t)SS * DM];

// split bf16 operands (hi + lo)
__device__ __nv_bfloat16 g_tgt_h[(size_t)BB * LL * DM];
__device__ __nv_bfloat16 g_tgt_l[(size_t)BB * LL * DM];
__device__ __nv_bfloat16 g_src_h[(size_t)SS * DL];
__device__ __nv_bfloat16 g_src_l[(size_t)SS * DL];
__device__ __nv_bfloat16 g_val_h[(size_t)SS * DL];
__device__ __nv_bfloat16 g_val_l[(size_t)SS * DL];
__device__ __nv_bfloat16 g_Wq_h[(size_t)DM * DM];
__device__ __nv_bfloat16 g_Wq_l[(size_t)DM * DM];
__device__ __nv_bfloat16 g_Wk_h[(size_t)DL * DM];
__device__ __nv_bfloat16 g_Wk_l[(size_t)DL * DM];
__device__ __nv_bfloat16 g_Wv_h[(size_t)DL * DM];
__device__ __nv_bfloat16 g_Wv_l[(size_t)DL * DM];
__device__ __nv_bfloat16 g_Wo_h[(size_t)DM * DL];
__device__ __nv_bfloat16 g_Wo_l[(size_t)DM * DL];
__device__ __nv_bfloat16 g_X_h[(size_t)BB * LL * DM];
__device__ __nv_bfloat16 g_X_l[(size_t)BB * LL * DM];

// ---------------------------------------------------------------------------
// fp32 -> (hi, lo) bf16 split, streaming. 8 floats per thread.
// ---------------------------------------------------------------------------
__global__ __launch_bounds__(256)
void split_kernel(const float4* __restrict__ in, uint4* __restrict__ hi,
                  uint4* __restrict__ lo, int n8)
{
    int i = blockIdx.x * 256 + threadIdx.x;
    if (i >= n8) return;
    float4 a = in[2 * i], b = in[2 * i + 1];
    float f[8] = {a.x, a.y, a.z, a.w, b.x, b.y, b.z, b.w};
    uint32_t hw[4], lw[4];
#pragma unroll
    for (int j = 0; j < 4; j++) {
        __nv_bfloat16 h0 = __float2bfloat16(f[2 * j]);
        __nv_bfloat16 h1 = __float2bfloat16(f[2 * j + 1]);
        __nv_bfloat16 l0 = __float2bfloat16(f[2 * j]     - __bfloat162float(h0));
        __nv_bfloat16 l1 = __float2bfloat16(f[2 * j + 1] - __bfloat162float(h1));
        __nv_bfloat162 H = __halves2bfloat162(h0, h1);
        __nv_bfloat162 L = __halves2bfloat162(l0, l1);
        hw[j] = *reinterpret_cast<uint32_t*>(&H);
        lw[j] = *reinterpret_cast<uint32_t*>(&L);
    }
    hi[i] = make_uint4(hw[0], hw[1], hw[2], hw[3]);
    lo[i] = make_uint4(lw[0], lw[1], lw[2], lw[3]);
}

// ---------------------------------------------------------------------------
// PTX helpers
// ---------------------------------------------------------------------------
__device__ __forceinline__ void cp16(uint32_t dst, const void* src, bool pred) {
    int sz = pred ? 16 : 0;
    asm volatile("cp.async.cg.shared.global [%0], [%1], 16, %2;\n"
                 :: "r"(dst), "l"(src), "r"(sz));
}
__device__ __forceinline__ void cp_commit() {
    asm volatile("cp.async.commit_group;\n");
}
template <int N> __device__ __forceinline__ void cp_wait() {
    asm volatile("cp.async.wait_group %0;\n" :: "n"(N));
}
__device__ __forceinline__ void ldsm4(uint32_t addr, uint32_t& r0, uint32_t& r1,
                                      uint32_t& r2, uint32_t& r3) {
    asm volatile("ldmatrix.sync.aligned.m8n8.x4.shared.b16 {%0,%1,%2,%3}, [%4];"
                 : "=r"(r0), "=r"(r1), "=r"(r2), "=r"(r3) : "r"(addr));
}
__device__ __forceinline__ void ldsm4t(uint32_t addr, uint32_t& r0, uint32_t& r1,
                                       uint32_t& r2, uint32_t& r3) {
    asm volatile("ldmatrix.sync.aligned.m8n8.x4.trans.shared.b16 {%0,%1,%2,%3}, [%4];"
                 : "=r"(r0), "=r"(r1), "=r"(r2), "=r"(r3) : "r"(addr));
}
__device__ __forceinline__ void mma16816(float* c, const uint32_t* a,
                                         uint32_t b0, uint32_t b1) {
    asm volatile(
        "mma.sync.aligned.m16n8k16.row.col.f32.bf16.bf16.f32 "
        "{%0,%1,%2,%3}, {%4,%5,%6,%7}, {%8,%9}, {%0,%1,%2,%3};"
        : "+f"(c[0]), "+f"(c[1]), "+f"(c[2]), "+f"(c[3])
        : "r"(a[0]), "r"(a[1]), "r"(a[2]), "r"(a[3]), "r"(b0), "r"(b1));
}

// ---------------------------------------------------------------------------
// Split-bf16 tensor-core GEMM on pre-split operands.
// C[M,N] = A @ B + bias;  A = Ah+Al ([M][K] bf16), B = Bh+Bl ([K][N] bf16).
// 128x128 tile, BK=32, 256 threads, cp.async double-buffered.
// A smem row-major (PADA), B smem k-major (PADB) + ldmatrix.trans.
// ---------------------------------------------------------------------------
#define PADA 40                 // 32 data + 8 pad bf16  (80 B rows)
#define PADB 136                // 128 data + 8 pad bf16 (272 B rows)
#define A_ST (128 * PADA)       // elems per A stage
#define B_ST (32 * PADB)        // elems per B stage
#define GSMEM ((4 * A_ST + 4 * B_ST) * 2)   // bytes = 75776

__global__ __launch_bounds__(256, 2)
void gemm_sp(const __nv_bfloat16* __restrict__ Ah, const __nv_bfloat16* __restrict__ Al,
             const __nv_bfloat16* __restrict__ Bh, const __nv_bfloat16* __restrict__ Bl,
             const float* __restrict__ bias, float* __restrict__ C,
             int M, int N, int K,
             const __nv_bfloat16* Ah2, const __nv_bfloat16* Al2,
             const __nv_bfloat16* Bh2, const __nv_bfloat16* Bl2,
             const float* bias2, float* C2)
{
    if (blockIdx.z) { Ah = Ah2; Al = Al2; Bh = Bh2; Bl = Bl2; bias = bias2; C = C2; }

    extern __shared__ __nv_bfloat16 sm[];
    __nv_bfloat16* sAh = sm;
    __nv_bfloat16* sAl = sm + 2 * A_ST;
    __nv_bfloat16* sBh = sm + 4 * A_ST;
    __nv_bfloat16* sBl = sm + 4 * A_ST + 2 * B_ST;

    const int tid  = threadIdx.x;
    const int lane = tid & 31;
    const int wid  = tid >> 5;
    const int wm   = wid >> 2;        // 0..1 : 64 rows
    const int wn   = wid & 3;         // 0..3 : 32 cols
    const int row0 = blockIdx.y * 128;
    const int col0 = blockIdx.x * 128;

    // ldmatrix lane addressing
    const int rF = lane & 15;                       // A: row within 16
    const int cF = (lane >> 4) << 3;                // A: k-half
    const int bR = ((lane >> 3) & 1) * 8 + (lane & 7);  // B: k-row within 16
    const int bC = (lane >> 4) << 3;                // B: n-half

    float acc[4][4][4];
#pragma unroll
    for (int a = 0; a < 4; a++)
#pragma unroll
        for (int b = 0; b < 4; b++)
#pragma unroll
            for (int c = 0; c < 4; c++) acc[a][b][c] = 0.f;

    const int KT = K >> 5;

    auto issue = [&](int kt) {
        const int k0 = kt << 5;
        const int st = kt & 1;
        __nv_bfloat16* dAh = sAh + st * A_ST;
        __nv_bfloat16* dAl = sAl + st * A_ST;
        __nv_bfloat16* dBh = sBh + st * B_ST;
        __nv_bfloat16* dBl = sBl + st * B_ST;
#pragma unroll
        for (int i = 0; i < 2; i++) {               // A: 128 rows x 64B
            int c   = tid + (i << 8);
            int row = c >> 2;
            int off = (c & 3) << 3;                 // elems
            bool p  = (row0 + row) < M;
            size_t go = (size_t)(row0 + (p ? row : 0)) * K + k0 + off;
            uint32_t d = (uint32_t)__cvta_generic_to_shared(dAh + row * PADA + off);
            cp16(d, Ah + go, p);
            d = (uint32_t)__cvta_generic_to_shared(dAl + row * PADA + off);
            cp16(d, Al + go, p);
        }
#pragma unroll
        for (int i = 0; i < 2; i++) {               // B: 32 rows x 256B
            int c   = tid + (i << 8);
            int row = c >> 4;
            int off = (c & 15) << 3;
            size_t go = (size_t)(k0 + row) * N + col0 + off;
            uint32_t d = (uint32_t)__cvta_generic_to_shared(dBh + row * PADB + off);
            cp16(d, Bh + go, true);
            d = (uint32_t)__cvta_generic_to_shared(dBl + row * PADB + off);
            cp16(d, Bl + go, true);
        }
        cp_commit();
    };

    auto compute = [&](int st) {
        const __nv_bfloat16* pAh = sAh + st * A_ST;
        const __nv_bfloat16* pAl = sAl + st * A_ST;
        const __nv_bfloat16* pBh = sBh + st * B_ST;
        const __nv_bfloat16* pBl = sBl + st * B_ST;
#pragma unroll
        for (int kk = 0; kk < 32; kk += 16) {
            uint32_t bh[2][4], bl[2][4];
#pragma unroll
            for (int p = 0; p < 2; p++) {
                int rr = kk + bR;
                int cc = wn * 32 + p * 16 + bC;
                ldsm4t((uint32_t)__cvta_generic_to_shared(pBh + rr * PADB + cc),
                       bh[p][0], bh[p][1], bh[p][2], bh[p][3]);
                ldsm4t((uint32_t)__cvta_generic_to_shared(pBl + rr * PADB + cc),
                       bl[p][0], bl[p][1], bl[p][2], bl[p][3]);
            }
#pragma unroll
            for (int mf = 0; mf < 4; mf++) {
                int r = wm * 64 + mf * 16 + rF;
                uint32_t ah[4], al[4];
                ldsm4((uint32_t)__cvta_generic_to_shared(pAh + r * PADA + kk + cF),
                      ah[0], ah[1], ah[2], ah[3]);
                ldsm4((uint32_t)__cvta_generic_to_shared(pAl + r * PADA + kk + cF),
                      al[0], al[1], al[2], al[3]);
#pragma unroll
                for (int p = 0; p < 2; p++) {
                    mma16816(acc[mf][2 * p],     ah, bh[p][0], bh[p][1]);
                    mma16816(acc[mf][2 * p],     al, bh[p][0], bh[p][1]);
                    mma16816(acc[mf][2 * p],     ah, bl[p][0], bl[p][1]);
                    mma16816(acc[mf][2 * p + 1], ah, bh[p][2], bh[p][3]);
                    mma16816(acc[mf][2 * p + 1], al, bh[p][2], bh[p][3]);
                    mma16816(acc[mf][2 * p + 1], ah, bl[p][2], bl[p][3]);
                }
            }
        }
    };

    issue(0);
    for (int kt = 0; kt < KT; kt++) {
        if (kt + 1 < KT) { issue(kt + 1); cp_wait<1>(); }
        else             { cp_wait<0>(); }
        __syncthreads();
        compute(kt & 1);
        __syncthreads();
    }

    // epilogue: bias + store
#pragma unroll
    for (int mf = 0; mf < 4; mf++) {
        int r = row0 + wm * 64 + mf * 16 + (lane >> 2);
#pragma unroll
        for (int half = 0; half < 2; half++) {
            int rr = r + half * 8;
            if (rr >= M) continue;
            float* crow = C + (size_t)rr * N;
#pragma unroll
            for (int nf = 0; nf < 4; nf++) {
                int cc = col0 + wn * 32 + nf * 8 + (lane & 3) * 2;
                float2 bv = *(const float2*)(bias + cc);
                float2 o;
                o.x = acc[mf][nf][half * 2 + 0] + bv.x;
                o.y = acc[mf][nf][half * 2 + 1] + bv.y;
                *(float2*)(crow + cc) = o;
            }
        }
    }
}

// ---------------------------------------------------------------------------
// Fused attention; writes X directly as split bf16 for the Wo GEMM.
// ---------------------------------------------------------------------------
#define ATS 64

__global__ __launch_bounds__(128)
void attn_kernel(const float* __restrict__ Q, const float* __restrict__ K,
                 const float* __restrict__ V,
                 __nv_bfloat16* __restrict__ Xh, __nv_bfloat16* __restrict__ Xl)
{
    __shared__ float Ks[ATS][EE];
    __shared__ float Vs[ATS][EE];

    const int tid = threadIdx.x;
    const int bh  = blockIdx.y;
    const int b   = bh >> 4;
    const int h   = bh & 15;
    const int l   = blockIdx.x * 128 + tid;
    const size_t r = (size_t)b * LL + l;

    float q[EE];
    {
        const float4* qp = (const float4*)(Q + r * DM + h * EE);
#pragma unroll
        for (int i = 0; i < EE / 4; i++) {
            float4 t = qp[i];
            q[4 * i + 0] = t.x; q[4 * i + 1] = t.y;
            q[4 * i + 2] = t.z; q[4 * i + 3] = t.w;
        }
    }

    float o[EE];
#pragma unroll
    for (int e = 0; e < EE; e++) o[e] = 0.f;
    float mx = -1e30f, ssum = 0.f;
    const float scale = 0.125f;

    for (int s0 = 0; s0 < SS; s0 += ATS) {
        const int cnt = min(ATS, SS - s0);
        __syncthreads();
        for (int i = tid; i < ATS * (EE / 4); i += 128) {
            int row = i >> 4;
            int c4  = (i & 15) * 4;
            float4 kv = make_float4(0.f, 0.f, 0.f, 0.f);
            float4 vv = make_float4(0.f, 0.f, 0.f, 0.f);
            if (row < cnt) {
                size_t base = (size_t)(s0 + row) * DM + h * EE + c4;
                kv = *(const float4*)(K + base);
                vv = *(const float4*)(V + base);
            }
            *(float4*)&Ks[row][c4] = kv;
            *(float4*)&Vs[row][c4] = vv;
        }
        __syncthreads();

        for (int j = 0; j < cnt; j++) {
            float s = 0.f;
            const float4* kr = (const float4*)Ks[j];
#pragma unroll
            for (int i = 0; i < EE / 4; i++) {
                float4 t = kr[i];
                s += q[4 * i + 0] * t.x + q[4 * i + 1] * t.y
                   + q[4 * i + 2] * t.z + q[4 * i + 3] * t.w;
            }
            s *= scale;
            if (s > mx) {
                float c = __expf(mx - s);
                ssum *= c;
#pragma unroll
                for (int e = 0; e < EE; e++) o[e] *= c;
                mx = s;
            }
            float p = __expf(s - mx);
            ssum += p;
            const float4* vr = (const float4*)Vs[j];
#pragma unroll
            for (int i = 0; i < EE / 4; i++) {
                float4 t = vr[i];
                o[4 * i + 0] += p * t.x; o[4 * i + 1] += p * t.y;
                o[4 * i + 2] += p * t.z; o[4 * i + 3] += p * t.w;
            }
        }
    }

    const float inv = 1.f / ssum;
    const size_t base = r * DM + h * EE;
#pragma unroll
    for (int i = 0; i < EE / 2; i++) {
        float v0 = o[2 * i] * inv, v1 = o[2 * i + 1] * inv;
        __nv_bfloat16 h0 = __float2bfloat16(v0);
        __nv_bfloat16 h1 = __float2bfloat16(v1);
        __nv_bfloat16 l0 = __float2bfloat16(v0 - __bfloat162float(h0));
        __nv_bfloat16 l1 = __float2bfloat16(v1 - __bfloat162float(h1));
        *(__nv_bfloat162*)(Xh + base + 2 * i) = __halves2bfloat162(h0, h1);
        *(__nv_bfloat162*)(Xl + base + 2 * i) = __halves2bfloat162(l0, l1);
    }
}

// ---------------------------------------------------------------------------
extern "C" void kernel_launch(void* const* d_in, const int* in_sizes, int n_in,
                              void* d_out, int out_size)
{
    const float* tgt = (const float*)d_in[0];
    const float* src = (const float*)d_in[1];
    const float* val = (const float*)d_in[2];
    const float* Wq  = (const float*)d_in[3];
    const float* bq  = (const float*)d_in[4];
    const float* Wk  = (const float*)d_in[5];
    const float* bk  = (const float*)d_in[6];
    const float* Wv  = (const float*)d_in[7];
    const float* bv  = (const float*)d_in[8];
    const float* Wo  = (const float*)d_in[9];
    const float* bo  = (const float*)d_in[10];
    float* out = (float*)d_out;

    float *Qb, *Kb, *Vb;
    cudaGetSymbolAddress((void**)&Qb, g_Q);
    cudaGetSymbolAddress((void**)&Kb, g_K);
    cudaGetSymbolAddress((void**)&Vb, g_V);

    __nv_bfloat16 *tgtH, *tgtL, *srcH, *srcL, *valH, *valL;
    __nv_bfloat16 *WqH, *WqL, *WkH, *WkL, *WvH, *WvL, *WoH, *WoL, *XH, *XL;
    cudaGetSymbolAddress((void**)&tgtH, g_tgt_h); cudaGetSymbolAddress((void**)&tgtL, g_tgt_l);
    cudaGetSymbolAddress((void**)&srcH, g_src_h); cudaGetSymbolAddress((void**)&srcL, g_src_l);
    cudaGetSymbolAddress((void**)&valH, g_val_h); cudaGetSymbolAddress((void**)&valL, g_val_l);
    cudaGetSymbolAddress((void**)&WqH, g_Wq_h);   cudaGetSymbolAddress((void**)&WqL, g_Wq_l);
    cudaGetSymbolAddress((void**)&WkH, g_Wk_h);   cudaGetSymbolAddress((void**)&WkL, g_Wk_l);
    cudaGetSymbolAddress((void**)&WvH, g_Wv_h);   cudaGetSymbolAddress((void**)&WvL, g_Wv_l);
    cudaGetSymbolAddress((void**)&WoH, g_Wo_h);   cudaGetSymbolAddress((void**)&WoL, g_Wo_l);
    cudaGetSymbolAddress((void**)&XH,  g_X_h);    cudaGetSymbolAddress((void**)&XL,  g_X_l);

    cudaFuncSetAttribute(gemm_sp, cudaFuncAttributeMaxDynamicSharedMemorySize, GSMEM);

    // ---- split pre-passes ----
    auto split = [](const float* p, __nv_bfloat16* h, __nv_bfloat16* l, size_t n) {
        int n8 = (int)(n / 8);
        split_kernel<<<(n8 + 255) / 256, 256>>>((const float4*)p, (uint4*)h, (uint4*)l, n8);
    };
    split(tgt, tgtH, tgtL, (size_t)BB * LL * DM);
    split(src, srcH, srcL, (size_t)SS * DL);
    split(val, valH, valL, (size_t)SS * DL);
    split(Wq,  WqH,  WqL,  (size_t)DM * DM);
    split(Wk,  WkH,  WkL,  (size_t)DL * DM);
    split(Wv,  WvH,  WvL,  (size_t)DL * DM);
    split(Wo,  WoH,  WoL,  (size_t)DM * DL);

    // ---- Q = tgt @ Wq + bq    M=8192, N=1024, K=1024 ----
    gemm_sp<<<dim3(DM / 128, (BB * LL) / 128, 1), 256, GSMEM>>>(
        tgtH, tgtL, WqH, WqL, bq, Qb, BB * LL, DM, DM,
        nullptr, nullptr, nullptr, nullptr, nullptr, nullptr);

    // ---- K/V projections fused (z=2)   M=1000, N=1024, K=4096 ----
    gemm_sp<<<dim3(DM / 128, (SS + 127) / 128, 2), 256, GSMEM>>>(
        srcH, srcL, WkH, WkL, bk, Kb, SS, DM, DL,
        valH, valL, WvH, WvL, bv, Vb);

    // ---- attention (writes split X) ----
    attn_kernel<<<dim3(LL / 128, BB * HH), 128>>>(Qb, Kb, Vb, XH, XL);

    // ---- out = X @ Wo + bo    M=8192, N=4096, K=1024 ----
    gemm_sp<<<dim3(DL / 128, (BB * LL) / 128, 1), 256, GSMEM>>>(
        XH, XL, WoH, WoL, bo, out, BB * LL, DL, DM,
        nullptr, nullptr, nullptr, nullptr, nullptr, nullptr);
}